// round 16
// baseline (speedup 1.0000x reference)
#include <cuda_runtime.h>
#include <cuda_fp16.h>
#include <cstdint>
#include <math.h>

// ---------------------------------------------------------------------------
// Problem constants (B=2, S=2048, D=1024, H=16)
// ---------------------------------------------------------------------------
#define BATCH   2
#define SEQ     2048
#define DMODEL  1024
#define NHEADS  16
#define DHEAD   64
#define WINDOW  256
#define MROWS   (BATCH * SEQ)   // 4096
#define DD      (DMODEL * DMODEL)

// ---------------------------------------------------------------------------
// Scratch (__device__ globals; allocation-free rule)
// ---------------------------------------------------------------------------
__device__ __half g_xhi [MROWS * DMODEL];
__device__ __half g_qhi [MROWS * DMODEL];
__device__ __half g_khi [MROWS * DMODEL];
__device__ __half g_vhi [MROWS * DMODEL];
__device__ __half g_aohi[MROWS * DMODEL];
__device__ __half g_wthi[4 * DD];   // transposed weights [N][K], fp16

// ---------------------------------------------------------------------------
// PTX helpers — base sm_100 ISA only (mma.sync / ldmatrix / cp.async / ex2)
// ---------------------------------------------------------------------------
__device__ __forceinline__ uint32_t smem_u32(const void* p) {
    uint32_t a;
    asm("{ .reg .u64 t; cvta.to.shared.u64 t, %1; cvt.u32.u64 %0, t; }" : "=r"(a) : "l"(p));
    return a;
}

#define CP_ASYNC16(dst, src) \
    asm volatile("cp.async.cg.shared.global [%0], [%1], 16;" :: "r"(dst), "l"(src))
#define CP_COMMIT() asm volatile("cp.async.commit_group;" ::: "memory")
#define CP_WAIT(n)  asm volatile("cp.async.wait_group %0;" :: "n"(n) : "memory")

#define LDSM_X4(r0, r1, r2, r3, addr) \
    asm volatile("ldmatrix.sync.aligned.m8n8.x4.shared.b16 {%0,%1,%2,%3}, [%4];" \
        : "=r"(r0), "=r"(r1), "=r"(r2), "=r"(r3) : "r"(addr))

#define LDSM_X4_T(r0, r1, r2, r3, addr) \
    asm volatile("ldmatrix.sync.aligned.m8n8.x4.trans.shared.b16 {%0,%1,%2,%3}, [%4];" \
        : "=r"(r0), "=r"(r1), "=r"(r2), "=r"(r3) : "r"(addr))

#define MMA16816(d, a0, a1, a2, a3, b0, b1) \
    asm volatile("mma.sync.aligned.m16n8k16.row.col.f32.f16.f16.f32 " \
        "{%0,%1,%2,%3}, {%4,%5,%6,%7}, {%8,%9}, {%0,%1,%2,%3};" \
        : "+f"((d)[0]), "+f"((d)[1]), "+f"((d)[2]), "+f"((d)[3]) \
        : "r"(a0), "r"(a1), "r"(a2), "r"(a3), "r"(b0), "r"(b1))

// fp16-accumulate variant: c/d are 2x b32 (4 packed halves)
#define MMA16816_H(d, a0, a1, a2, a3, b0, b1) \
    asm volatile("mma.sync.aligned.m16n8k16.row.col.f16.f16.f16.f16 " \
        "{%0,%1}, {%2,%3,%4,%5}, {%6,%7}, {%0,%1};" \
        : "+r"((d)[0]), "+r"((d)[1]) \
        : "r"(a0), "r"(a1), "r"(a2), "r"(a3), "r"(b0), "r"(b1))

__device__ __forceinline__ uint32_t pack2h(float x, float y) {
    __half2 h2(__float2half_rn(x), __float2half_rn(y));
    return *(uint32_t*)&h2;
}

// packed 2^x for a pair of fp32 -> fp16x2 fragment (one MUFU op per pair)
__device__ __forceinline__ uint32_t ex2_f16x2(float x, float y) {
    uint32_t h;
    asm("{ .reg .b32 t; cvt.rn.f16x2.f32 t, %2, %1; ex2.approx.f16x2 %0, t; }"
        : "=r"(h) : "f"(x), "f"(y));   // lo = x, hi = y
    return h;
}
__device__ __forceinline__ float ex2f(float x) {
    float r;
    asm("ex2.approx.f32 %0, %1;" : "=f"(r) : "f"(x));
    return r;
}

// ---------------------------------------------------------------------------
// Prep: z=0..3 -> weight transpose+cvt ([KxN] fp32 -> [NxK] fp16);
//       z=4    -> X fp32 -> fp16 elementwise convert.
// grid (32, 32, 5), block (32, 8)
// ---------------------------------------------------------------------------
__global__ __launch_bounds__(256) void prep_kernel(
    const float* __restrict__ X,
    const float* __restrict__ w0, const float* __restrict__ w1,
    const float* __restrict__ w2, const float* __restrict__ w3,
    __half* __restrict__ xh, __half* __restrict__ hi)
{
    const int z = blockIdx.z;
    const int tx = threadIdx.x, ty = threadIdx.y;

    if (z == 4) {
        const int bid = blockIdx.y * 32 + blockIdx.x;
        const int tid = ty * 32 + tx;
#pragma unroll
        for (int it = 0; it < 4; it++) {
            int i = bid * 1024 + it * 256 + tid;
            float4 v = ((const float4*)X)[i];
            ((uint32_t*)xh)[2*i]   = pack2h(v.x, v.y);
            ((uint32_t*)xh)[2*i+1] = pack2h(v.z, v.w);
        }
        return;
    }

    __shared__ float t[32][33];
    const float* in = (z == 0) ? w0 : (z == 1) ? w1 : (z == 2) ? w2 : w3;
    __half* oh = hi + (size_t)z * DD;
    int bx = blockIdx.x * 32, by = blockIdx.y * 32;
#pragma unroll
    for (int j = ty; j < 32; j += 8)
        t[j][tx] = in[(size_t)(by + j) * DMODEL + bx + tx];
    __syncthreads();
#pragma unroll
    for (int j = ty; j < 32; j += 8) {
        float v = t[tx][j];                 // = in[by+tx][bx+j]
        oh[(size_t)(bx + j) * DMODEL + by + tx] = __float2half_rn(v);
    }
}

// ---------------------------------------------------------------------------
// GEMM, 128x128 CTA tile, BK=32, 256 threads, 2 CTAs/SM, 4-stage cp.async.
// fp16-accumulate mma into hacc (2 regs/tile); spilled into fp32 acc every
// 2 chunks (64-K window) to bound rounding error.
// ---------------------------------------------------------------------------
#define G_RS       80          // row stride bytes (32 fp16 = 64B + 16B pad)
#define G_TILE_B   (128 * G_RS)          // 10240
#define Q_STAGE_B  (2 * G_TILE_B)        // Ah, Bh
#define Q_SMEM_B   (4 * Q_STAGE_B)       // 81920

// one 32-K chunk from stage base s0 into hacc[4][4][2] (fp16 acc)
#define GEMM_CHUNK_H(s0)                                                        \
    do {                                                                        \
        const uint32_t sAh = (s0), sBh = (s0) + G_TILE_B;                       \
        _Pragma("unroll")                                                       \
        for (int ks = 0; ks < 2; ks++) {                                        \
            const uint32_t kb = ks * 32;                                        \
            uint32_t bfr[4][2];                                                 \
            _Pragma("unroll")                                                   \
            for (int np = 0; np < 2; np++) {                                    \
                uint32_t ro = (wn0 + np * 16 + (lane & 7) + ((lane >> 4) & 1) * 8) * G_RS \
                              + kb + ((lane >> 3) & 1) * 16;                    \
                LDSM_X4(bfr[np*2][0], bfr[np*2][1],                             \
                        bfr[np*2+1][0], bfr[np*2+1][1], sBh + ro);              \
            }                                                                   \
            uint32_t afr[4][4];                                                 \
            _Pragma("unroll")                                                   \
            for (int mi = 0; mi < 4; mi++) {                                    \
                uint32_t ro = (wm0 + mi * 16 + (lane & 15)) * G_RS + kb + (lane >> 4) * 16; \
                LDSM_X4(afr[mi][0], afr[mi][1], afr[mi][2], afr[mi][3], sAh + ro); \
            }                                                                   \
            _Pragma("unroll")                                                   \
            for (int mi = 0; mi < 4; mi++)                                      \
                _Pragma("unroll")                                               \
                for (int ni = 0; ni < 4; ni++)                                  \
                    MMA16816_H(hacc[mi][ni], afr[mi][0], afr[mi][1], afr[mi][2],\
                               afr[mi][3], bfr[ni][0], bfr[ni][1]);             \
        }                                                                       \
    } while (0)

// drain fp16 window accumulators into fp32
#define GEMM_SPILL()                                                            \
    do {                                                                        \
        _Pragma("unroll")                                                       \
        for (int mi = 0; mi < 4; mi++)                                          \
            _Pragma("unroll")                                                   \
            for (int ni = 0; ni < 4; ni++) {                                    \
                float2 f0 = __half22float2(*(__half2*)&hacc[mi][ni][0]);        \
                float2 f1 = __half22float2(*(__half2*)&hacc[mi][ni][1]);        \
                acc[mi][ni][0] += f0.x; acc[mi][ni][1] += f0.y;                 \
                acc[mi][ni][2] += f1.x; acc[mi][ni][3] += f1.y;                 \
                hacc[mi][ni][0] = 0u;   hacc[mi][ni][1] = 0u;                   \
            }                                                                   \
    } while (0)

// loader: per thread 2 rows x 16B for A and B each
#define GEMM_ISSUE_LOAD(st, kt, Aptr, Bptr)                                     \
    do {                                                                        \
        uint32_t s0 = sb + (st) * Q_STAGE_B;                                    \
        _Pragma("unroll")                                                       \
        for (int u = 0; u < 2; u++) {                                           \
            int row = u ? r1l : r0l;                                            \
            uint32_t so = row * G_RS + c16a * 2;                                \
            CP_ASYNC16(s0 + 0 * G_TILE_B + so,                                  \
                       (Aptr) + (size_t)(brow + row) * K + (kt) + c16a);        \
            CP_ASYNC16(s0 + 1 * G_TILE_B + so,                                  \
                       (Bptr) + (size_t)(bcol + row) * K + (kt) + c16a);        \
        }                                                                       \
    } while (0)

#define GEMM_MAINLOOP(Aptr, Bptr)                                               \
    do {                                                                        \
        const int nchunks = K / 32;                                             \
        GEMM_ISSUE_LOAD(0, 0,  (Aptr), (Bptr));  CP_COMMIT();                   \
        GEMM_ISSUE_LOAD(1, 32, (Aptr), (Bptr));  CP_COMMIT();                   \
        for (int ch = 0; ch < nchunks; ch++) {                                  \
            if (ch + 2 < nchunks) {                                             \
                GEMM_ISSUE_LOAD((ch + 2) & 3, (ch + 2) * 32, (Aptr), (Bptr));   \
                CP_COMMIT();                                                    \
                CP_WAIT(2);                                                     \
            } else if (ch + 1 < nchunks) {                                      \
                CP_WAIT(1);                                                     \
            } else {                                                            \
                CP_WAIT(0);                                                     \
            }                                                                   \
            __syncthreads();                                                    \
            GEMM_CHUNK_H(sb + (ch & 3) * Q_STAGE_B);                            \
            if (ch & 1) GEMM_SPILL();                                           \
        }                                                                       \
    } while (0)

// ---------------------------------------------------------------------------
// QKV GEMM: grid (N/128, M/128, 3); z selects W/bias/output; fp16 out.
// ---------------------------------------------------------------------------
__global__ __launch_bounds__(256, 2) void gemm_qkv(
    const __half* __restrict__ Ahi, const __half* __restrict__ Wt,
    const float* __restrict__ bq, const float* __restrict__ bk,
    const float* __restrict__ bv,
    __half* __restrict__ Qhi, __half* __restrict__ Khi, __half* __restrict__ Vhi,
    int M, int N, int K)
{
    extern __shared__ char smem[];
    const uint32_t sb = smem_u32(smem);
    const int z = blockIdx.z;
    const __half* Bh = Wt + (size_t)z * DD;
    const float* bias = (z == 0) ? bq : (z == 1) ? bk : bv;
    __half* Chi = (z == 0) ? Qhi : (z == 1) ? Khi : Vhi;

    const int tid = threadIdx.x, lane = tid & 31, wid = tid >> 5;
    const int brow = blockIdx.y * 128, bcol = blockIdx.x * 128;
    const int wm0 = (wid & 1) * 64;
    const int wn0 = (wid >> 1) * 32;

    float acc[4][4][4];
    uint32_t hacc[4][4][2];
#pragma unroll
    for (int mi = 0; mi < 4; mi++)
#pragma unroll
        for (int ni = 0; ni < 4; ni++) {
#pragma unroll
            for (int e = 0; e < 4; e++) acc[mi][ni][e] = 0.f;
            hacc[mi][ni][0] = 0u; hacc[mi][ni][1] = 0u;
        }

    const int r0l = tid >> 2, c16a = (tid & 3) * 8;
    const int r1l = (tid + 256) >> 2;

    GEMM_MAINLOOP(Ahi, Bh);

    // epilogue: fp16 out
#pragma unroll
    for (int mi = 0; mi < 4; mi++) {
#pragma unroll
        for (int ni = 0; ni < 4; ni++) {
            int r = brow + wm0 + mi * 16 + (lane >> 2);
            int c = bcol + wn0 + ni * 8 + (lane & 3) * 2;
            float bx = bias[c], by = bias[c + 1];
            *(uint32_t*)&Chi[(size_t)r * N + c] =
                pack2h(acc[mi][ni][0] + bx, acc[mi][ni][1] + by);
            *(uint32_t*)&Chi[(size_t)(r + 8) * N + c] =
                pack2h(acc[mi][ni][2] + bx, acc[mi][ni][3] + by);
        }
    }
}

// ---------------------------------------------------------------------------
// O-projection GEMM: fp32 out; same mainloop.
// ---------------------------------------------------------------------------
__global__ __launch_bounds__(256, 2) void gemm_o(
    const __half* __restrict__ Ahi, const __half* __restrict__ Bhi,
    const float* __restrict__ bias, float* __restrict__ C,
    int M, int N, int K)
{
    extern __shared__ char smem[];
    const uint32_t sb = smem_u32(smem);
    const int tid = threadIdx.x, lane = tid & 31, wid = tid >> 5;
    const int brow = blockIdx.y * 128, bcol = blockIdx.x * 128;
    const int wm0 = (wid & 1) * 64;
    const int wn0 = (wid >> 1) * 32;

    float acc[4][4][4];
    uint32_t hacc[4][4][2];
#pragma unroll
    for (int mi = 0; mi < 4; mi++)
#pragma unroll
        for (int ni = 0; ni < 4; ni++) {
#pragma unroll
            for (int e = 0; e < 4; e++) acc[mi][ni][e] = 0.f;
            hacc[mi][ni][0] = 0u; hacc[mi][ni][1] = 0u;
        }

    const int r0l = tid >> 2, c16a = (tid & 3) * 8;
    const int r1l = (tid + 256) >> 2;

    GEMM_MAINLOOP(Ahi, Bhi);

#pragma unroll
    for (int mi = 0; mi < 4; mi++) {
#pragma unroll
        for (int ni = 0; ni < 4; ni++) {
            int r = brow + wm0 + mi * 16 + (lane >> 2);
            int c = bcol + wn0 + ni * 8 + (lane & 3) * 2;
            float bx = bias[c], by = bias[c + 1];
            *(float2*)&C[(size_t)r * N + c] =
                make_float2(acc[mi][ni][0] + bx, acc[mi][ni][1] + by);
            *(float2*)&C[(size_t)(r + 8) * N + c] =
                make_float2(acc[mi][ni][2] + bx, acc[mi][ni][3] + by);
        }
    }
}

// ---------------------------------------------------------------------------
// Tensor-core banded attention (fp16, 1-pass QK and PV), base-2 softmax with
// packed ex2.approx.f16x2. (Unchanged from R15; fp32-acc mma kept here.)
// grid = (S/128, H, B), block = 256 (8 warps x 16 q-rows). fp16 output.
// ---------------------------------------------------------------------------
#define AT_RS    144                 // smem row stride bytes (72 fp16)
#define AT_QTILE (128 * AT_RS)       // 18432 B (Q: 128 rows)
#define AT_KTILE (64 * AT_RS)        // 9216 B  (K or V: 64 rows)
#define AT_SQH   0
#define AT_ST0   AT_QTILE
#define AT_STB   (2 * AT_KTILE)      // Kh, Vh per stage
#define AT_SMEM  (AT_QTILE + 2 * AT_STB)   // 55296 B

__global__ __launch_bounds__(256) void attn_tc(
    const __half* __restrict__ Qh, const __half* __restrict__ Kh,
    const __half* __restrict__ Vh, __half* __restrict__ Oh)
{
    extern __shared__ char smem[];
    const uint32_t sb = smem_u32(smem);
    const int qt = blockIdx.x, h = blockIdx.y, b = blockIdx.z;
    const int q0 = qt * 128;
    const int tid = threadIdx.x, lane = tid & 31, w = tid >> 5;
    const float scale_l2e = 0.125f * 1.4426950408889634f;  // scale * log2(e)

    const int qrow = tid >> 1;
    const int qhalf = (tid & 1) * 64;
    const int krow = tid >> 2;
    const int kquar = (tid & 3) * 32;

    const int kb_lo = max(0, q0 - (WINDOW - 1)) >> 6;
    const int kb_hi = (q0 + 127) >> 6;
    const int nch = kb_hi - kb_lo + 1;

    // prologue: Q + first K/V chunk
    {
        size_t g = ((size_t)(b * SEQ + q0 + qrow)) * DMODEL + h * DHEAD + (qhalf >> 1);
        uint32_t so = qrow * AT_RS + qhalf;
#pragma unroll
        for (int i = 0; i < 4; i++)
            CP_ASYNC16(sb + AT_SQH + so + i * 16, Qh + g + i * 8);
        size_t gk = ((size_t)(b * SEQ + kb_lo * 64 + krow)) * DMODEL + h * DHEAD + (kquar >> 1);
        uint32_t sko = krow * AT_RS + kquar;
        uint32_t s0 = sb + AT_ST0;
#pragma unroll
        for (int i = 0; i < 2; i++) {
            CP_ASYNC16(s0 + 0 * AT_KTILE + sko + i * 16, Kh + gk + i * 8);
            CP_ASYNC16(s0 + 1 * AT_KTILE + sko + i * 16, Vh + gk + i * 8);
        }
        CP_COMMIT();
    }

    float m0 = -1e30f, m1 = -1e30f, l0 = 0.f, l1 = 0.f;   // m in log2 domain
    float oacc[8][4];
#pragma unroll
    for (int t = 0; t < 8; t++)
#pragma unroll
        for (int e = 0; e < 4; e++) oacc[t][e] = 0.f;

    const int r0g = q0 + w * 16 + (lane >> 2);
    const int r1g = r0g + 8;
    const int wlo = q0 + w * 16;
    const int whi = wlo + 15;

    for (int i = 0; i < nch; i++) {
        const int kb = kb_lo + i;
        if (i + 1 < nch) {
            size_t gk = ((size_t)(b * SEQ + (kb + 1) * 64 + krow)) * DMODEL + h * DHEAD + (kquar >> 1);
            uint32_t sko = krow * AT_RS + kquar;
            uint32_t s0 = sb + AT_ST0 + ((i + 1) & 1) * AT_STB;
#pragma unroll
            for (int u = 0; u < 2; u++) {
                CP_ASYNC16(s0 + 0 * AT_KTILE + sko + u * 16, Kh + gk + u * 8);
                CP_ASYNC16(s0 + 1 * AT_KTILE + sko + u * 16, Vh + gk + u * 8);
            }
            CP_COMMIT();
            CP_WAIT(1);
        } else {
            CP_WAIT(0);
        }
        __syncthreads();

        const int kbase = kb * 64;
        if (kbase <= whi && kbase + 63 >= wlo - (WINDOW - 1)) {
            const uint32_t s0  = sb + AT_ST0 + (i & 1) * AT_STB;
            const uint32_t sKh = s0;
            const uint32_t sVh = s0 + AT_KTILE;

            // ---- S = Q K^T (1-pass) ----
            float sacc[8][4];
#pragma unroll
            for (int t = 0; t < 8; t++)
#pragma unroll
                for (int e = 0; e < 4; e++) sacc[t][e] = 0.f;

#pragma unroll
            for (int ks = 0; ks < 4; ks++) {
                const uint32_t kbb = ks * 32;
                uint32_t aro = (w * 16 + (lane & 15)) * AT_RS + kbb + (lane >> 4) * 16;
                uint32_t ah[4];
                LDSM_X4(ah[0], ah[1], ah[2], ah[3], sb + AT_SQH + aro);
#pragma unroll
                for (int np = 0; np < 4; np++) {
                    uint32_t ro = (np * 16 + (lane & 7) + ((lane >> 4) & 1) * 8) * AT_RS
                                  + kbb + ((lane >> 3) & 1) * 16;
                    uint32_t bh[4];
                    LDSM_X4(bh[0], bh[1], bh[2], bh[3], sKh + ro);
                    MMA16816(sacc[2*np],   ah[0], ah[1], ah[2], ah[3], bh[0], bh[1]);
                    MMA16816(sacc[2*np+1], ah[0], ah[1], ah[2], ah[3], bh[2], bh[3]);
                }
            }

            // ---- mask (base-2 domain) + row max ----
            float cmax0 = -1e30f, cmax1 = -1e30f;
#pragma unroll
            for (int t = 0; t < 8; t++) {
                const int c0 = kbase + t * 8 + 2 * (lane & 3);
                int d00 = r0g - c0, d01 = r0g - (c0 + 1);
                int d10 = r1g - c0, d11 = r1g - (c0 + 1);
                sacc[t][0] = (d00 >= 0 && d00 < WINDOW) ? sacc[t][0] * scale_l2e : -1e30f;
                sacc[t][1] = (d01 >= 0 && d01 < WINDOW) ? sacc[t][1] * scale_l2e : -1e30f;
                sacc[t][2] = (d10 >= 0 && d10 < WINDOW) ? sacc[t][2] * scale_l2e : -1e30f;
                sacc[t][3] = (d11 >= 0 && d11 < WINDOW) ? sacc[t][3] * scale_l2e : -1e30f;
                cmax0 = fmaxf(cmax0, fmaxf(sacc[t][0], sacc[t][1]));
                cmax1 = fmaxf(cmax1, fmaxf(sacc[t][2], sacc[t][3]));
            }
            cmax0 = fmaxf(cmax0, __shfl_xor_sync(0xffffffffu, cmax0, 1));
            cmax0 = fmaxf(cmax0, __shfl_xor_sync(0xffffffffu, cmax0, 2));
            cmax1 = fmaxf(cmax1, __shfl_xor_sync(0xffffffffu, cmax1, 1));
            cmax1 = fmaxf(cmax1, __shfl_xor_sync(0xffffffffu, cmax1, 2));

            float mn0 = fmaxf(m0, cmax0), mn1 = fmaxf(m1, cmax1);
            float a0 = ex2f(m0 - mn0), a1 = ex2f(m1 - mn1);

            // ---- packed 2^x -> fp16 P fragments; fp32 row-sums of the same p ----
            uint32_t ph[8][2];
            float rs0 = 0.f, rs1 = 0.f;
#pragma unroll
            for (int t = 0; t < 8; t++) {
                ph[t][0] = ex2_f16x2(sacc[t][0] - mn0, sacc[t][1] - mn0);
                ph[t][1] = ex2_f16x2(sacc[t][2] - mn1, sacc[t][3] - mn1);
                float2 f0 = __half22float2(*(__half2*)&ph[t][0]);
                float2 f1 = __half22float2(*(__half2*)&ph[t][1]);
                rs0 += f0.x + f0.y;
                rs1 += f1.x + f1.y;
            }
            rs0 += __shfl_xor_sync(0xffffffffu, rs0, 1);
            rs0 += __shfl_xor_sync(0xffffffffu, rs0, 2);
            rs1 += __shfl_xor_sync(0xffffffffu, rs1, 1);
            rs1 += __shfl_xor_sync(0xffffffffu, rs1, 2);
            l0 = l0 * a0 + rs0;  m0 = mn0;
            l1 = l1 * a1 + rs1;  m1 = mn1;
#pragma unroll
            for (int t = 0; t < 8; t++) {
                oacc[t][0] *= a0; oacc[t][1] *= a0;
                oacc[t][2] *= a1; oacc[t][3] *= a1;
            }

            // ---- PV (P fragments already fp16; V via ldmatrix.trans) ----
#pragma unroll
            for (int ks = 0; ks < 4; ks++) {
                uint32_t aph[4];
                aph[0] = ph[2*ks][0];
                aph[1] = ph[2*ks][1];
                aph[2] = ph[2*ks+1][0];
                aph[3] = ph[2*ks+1][1];
#pragma unroll
                for (int np = 0; np < 4; np++) {
                    uint32_t vro = (ks * 16 + (lane & 7) + ((lane >> 3) & 1) * 8) * AT_RS
                                   + np * 32 + (lane >> 4) * 16;
                    uint32_t vh[4];
                    LDSM_X4_T(vh[0], vh[1], vh[2], vh[3], sVh + vro);
                    MMA16816(oacc[2*np],   aph[0], aph[1], aph[2], aph[3], vh[0], vh[1]);
                    MMA16816(oacc[2*np+1], aph[0], aph[1], aph[2], aph[3], vh[2], vh[3]);
                }
            }
        }
        __syncthreads();
    }

    // ---- epilogue: divide by l, plain fp16 store ----
    const float inv0 = 1.f / l0, inv1 = 1.f / l1;
    const size_t row0 = (size_t)(b * SEQ + r0g) * DMODEL;
    const size_t row1 = (size_t)(b * SEQ + r1g) * DMODEL;
#pragma unroll
    for (int t = 0; t < 8; t++) {
        const int c = h * DHEAD + t * 8 + 2 * (lane & 3);
        *(uint32_t*)&Oh[row0 + c] = pack2h(oacc[t][0] * inv0, oacc[t][1] * inv0);
        *(uint32_t*)&Oh[row1 + c] = pack2h(oacc[t][2] * inv1, oacc[t][3] * inv1);
    }
}

// ---------------------------------------------------------------------------
// Launch
// ---------------------------------------------------------------------------
extern "C" void kernel_launch(void* const* d_in, const int* in_sizes, int n_in,
                              void* d_out, int out_size)
{
    const float* X  = (const float*)d_in[0];
    const float* Wq = (const float*)d_in[1];
    const float* bq = (const float*)d_in[2];
    const float* Wk = (const float*)d_in[3];
    const float* bk = (const float*)d_in[4];
    const float* Wv = (const float*)d_in[5];
    const float* bv = (const float*)d_in[6];
    const float* Wo = (const float*)d_in[7];
    const float* bo = (const float*)d_in[8];
    float* out = (float*)d_out;

    __half *xhi, *qhi, *khi, *vhi, *aohi, *wthi;
    cudaGetSymbolAddress((void**)&xhi,  g_xhi);
    cudaGetSymbolAddress((void**)&qhi,  g_qhi);
    cudaGetSymbolAddress((void**)&khi,  g_khi);
    cudaGetSymbolAddress((void**)&vhi,  g_vhi);
    cudaGetSymbolAddress((void**)&aohi, g_aohi);
    cudaGetSymbolAddress((void**)&wthi, g_wthi);

    cudaFuncSetAttribute(attn_tc,  cudaFuncAttributeMaxDynamicSharedMemorySize, AT_SMEM);
    cudaFuncSetAttribute(gemm_qkv, cudaFuncAttributeMaxDynamicSharedMemorySize, Q_SMEM_B);
    cudaFuncSetAttribute(gemm_o,   cudaFuncAttributeMaxDynamicSharedMemorySize, Q_SMEM_B);

    // 1. prep: X convert + all 4 weight transposes in one launch
    prep_kernel<<<dim3(32, 32, 5), dim3(32, 8)>>>(X, Wq, Wk, Wv, Wo, xhi, wthi);

    // 2. fused Q/K/V projections (fp16-acc mma + 64K fp32 spill)
    gemm_qkv<<<dim3(DMODEL / 128, MROWS / 128, 3), 256, Q_SMEM_B>>>(
        xhi, wthi, bq, bk, bv, qhi, khi, vhi, MROWS, DMODEL, DMODEL);

    // 3. tensor-core banded attention (128-query tiles, f16x2 ex2 softmax)
    attn_tc<<<dim3(SEQ / 128, NHEADS, BATCH), 256, AT_SMEM>>>(qhi, khi, vhi, aohi);

    // 4. O projection (fp16-acc mma + 64K fp32 spill) -> fp32 output
    gemm_o<<<dim3(DMODEL / 128, MROWS / 128), 256, Q_SMEM_B>>>(
        aohi, wthi + 3 * DD, bo, out, MROWS, DMODEL, DMODEL);
}

// round 17
// speedup vs baseline: 1.0946x; 1.0946x over previous
#include <cuda_runtime.h>
#include <cuda_fp16.h>
#include <cstdint>
#include <math.h>

// ---------------------------------------------------------------------------
// Problem constants (B=2, S=2048, D=1024, H=16)
// ---------------------------------------------------------------------------
#define BATCH   2
#define SEQ     2048
#define DMODEL  1024
#define NHEADS  16
#define DHEAD   64
#define WINDOW  256
#define MROWS   (BATCH * SEQ)   // 4096
#define DD      (DMODEL * DMODEL)

// ---------------------------------------------------------------------------
// Scratch (__device__ globals; allocation-free rule)
// ---------------------------------------------------------------------------
__device__ __half g_xhi [MROWS * DMODEL];
__device__ __half g_qhi [MROWS * DMODEL];
__device__ __half g_khi [MROWS * DMODEL];
__device__ __half g_vhi [MROWS * DMODEL];
__device__ __half g_aohi[MROWS * DMODEL];
__device__ __half g_wthi[4 * DD];   // transposed weights [N][K], fp16

// ---------------------------------------------------------------------------
// PTX helpers — base sm_100 ISA only (mma.sync / ldmatrix / cp.async / ex2)
// ---------------------------------------------------------------------------
__device__ __forceinline__ uint32_t smem_u32(const void* p) {
    uint32_t a;
    asm("{ .reg .u64 t; cvta.to.shared.u64 t, %1; cvt.u32.u64 %0, t; }" : "=r"(a) : "l"(p));
    return a;
}

#define CP_ASYNC16(dst, src) \
    asm volatile("cp.async.cg.shared.global [%0], [%1], 16;" :: "r"(dst), "l"(src))
#define CP_COMMIT() asm volatile("cp.async.commit_group;" ::: "memory")
#define CP_WAIT(n)  asm volatile("cp.async.wait_group %0;" :: "n"(n) : "memory")

#define LDSM_X4(r0, r1, r2, r3, addr) \
    asm volatile("ldmatrix.sync.aligned.m8n8.x4.shared.b16 {%0,%1,%2,%3}, [%4];" \
        : "=r"(r0), "=r"(r1), "=r"(r2), "=r"(r3) : "r"(addr))

#define LDSM_X4_T(r0, r1, r2, r3, addr) \
    asm volatile("ldmatrix.sync.aligned.m8n8.x4.trans.shared.b16 {%0,%1,%2,%3}, [%4];" \
        : "=r"(r0), "=r"(r1), "=r"(r2), "=r"(r3) : "r"(addr))

#define MMA16816(d, a0, a1, a2, a3, b0, b1) \
    asm volatile("mma.sync.aligned.m16n8k16.row.col.f32.f16.f16.f32 " \
        "{%0,%1,%2,%3}, {%4,%5,%6,%7}, {%8,%9}, {%0,%1,%2,%3};" \
        : "+f"((d)[0]), "+f"((d)[1]), "+f"((d)[2]), "+f"((d)[3]) \
        : "r"(a0), "r"(a1), "r"(a2), "r"(a3), "r"(b0), "r"(b1))

__device__ __forceinline__ uint32_t pack2h(float x, float y) {
    __half2 h2(__float2half_rn(x), __float2half_rn(y));
    return *(uint32_t*)&h2;
}

// packed 2^x for a pair of fp32 -> fp16x2 fragment (one MUFU op per pair)
__device__ __forceinline__ uint32_t ex2_f16x2(float x, float y) {
    uint32_t h;
    asm("{ .reg .b32 t; cvt.rn.f16x2.f32 t, %2, %1; ex2.approx.f16x2 %0, t; }"
        : "=r"(h) : "f"(x), "f"(y));   // lo = x, hi = y
    return h;
}
__device__ __forceinline__ float ex2f(float x) {
    float r;
    asm("ex2.approx.f32 %0, %1;" : "=f"(r) : "f"(x));
    return r;
}

// ---------------------------------------------------------------------------
// Prep: z=0..3 -> weight transpose+cvt ([KxN] fp32 -> [NxK] fp16);
//       z=4    -> X fp32 -> fp16 elementwise convert.
// grid (32, 32, 5), block (32, 8)
// ---------------------------------------------------------------------------
__global__ __launch_bounds__(256) void prep_kernel(
    const float* __restrict__ X,
    const float* __restrict__ w0, const float* __restrict__ w1,
    const float* __restrict__ w2, const float* __restrict__ w3,
    __half* __restrict__ xh, __half* __restrict__ hi)
{
    const int z = blockIdx.z;
    const int tx = threadIdx.x, ty = threadIdx.y;

    if (z == 4) {
        const int bid = blockIdx.y * 32 + blockIdx.x;
        const int tid = ty * 32 + tx;
#pragma unroll
        for (int it = 0; it < 4; it++) {
            int i = bid * 1024 + it * 256 + tid;
            float4 v = ((const float4*)X)[i];
            ((uint32_t*)xh)[2*i]   = pack2h(v.x, v.y);
            ((uint32_t*)xh)[2*i+1] = pack2h(v.z, v.w);
        }
        return;
    }

    __shared__ float t[32][33];
    const float* in = (z == 0) ? w0 : (z == 1) ? w1 : (z == 2) ? w2 : w3;
    __half* oh = hi + (size_t)z * DD;
    int bx = blockIdx.x * 32, by = blockIdx.y * 32;
#pragma unroll
    for (int j = ty; j < 32; j += 8)
        t[j][tx] = in[(size_t)(by + j) * DMODEL + bx + tx];
    __syncthreads();
#pragma unroll
    for (int j = ty; j < 32; j += 8) {
        float v = t[tx][j];                 // = in[by+tx][bx+j]
        oh[(size_t)(bx + j) * DMODEL + by + tx] = __float2half_rn(v);
    }
}

// ---------------------------------------------------------------------------
// GEMM (1-pass fp16), 128x128 CTA tile, BK=32, 256 threads, 2 CTAs/SM.
// (Proven R11 config, verbatim.) 4-stage cp.async pipeline, one __syncthreads
// per chunk (issue ch+2 -> commit -> wait(2) -> sync -> compute).
// ---------------------------------------------------------------------------
#define G_RS       80          // row stride bytes (32 fp16 = 64B + 16B pad)
#define G_TILE_B   (128 * G_RS)          // 10240
#define Q_STAGE_B  (2 * G_TILE_B)        // Ah, Bh
#define Q_SMEM_B   (4 * Q_STAGE_B)       // 81920

// compute one 32-K chunk from stage base s0 into acc[4][4][4]
#define GEMM_CHUNK(s0)                                                          \
    do {                                                                        \
        const uint32_t sAh = (s0), sBh = (s0) + G_TILE_B;                       \
        uint32_t bfr[2][4][2];                                                  \
        _Pragma("unroll")                                                       \
        for (int ks = 0; ks < 2; ks++) {                                        \
            const uint32_t kb = ks * 32;                                        \
            _Pragma("unroll")                                                   \
            for (int np = 0; np < 2; np++) {                                    \
                uint32_t ro = (wn0 + np * 16 + (lane & 7) + ((lane >> 4) & 1) * 8) * G_RS \
                              + kb + ((lane >> 3) & 1) * 16;                    \
                LDSM_X4(bfr[ks][np*2][0], bfr[ks][np*2][1],                     \
                        bfr[ks][np*2+1][0], bfr[ks][np*2+1][1], sBh + ro);      \
            }                                                                   \
        }                                                                       \
        _Pragma("unroll")                                                       \
        for (int ks = 0; ks < 2; ks++) {                                        \
            const uint32_t kb = ks * 32;                                        \
            uint32_t afr[4][4];                                                 \
            _Pragma("unroll")                                                   \
            for (int mi = 0; mi < 4; mi++) {                                    \
                uint32_t ro = (wm0 + mi * 16 + (lane & 15)) * G_RS + kb + (lane >> 4) * 16; \
                LDSM_X4(afr[mi][0], afr[mi][1], afr[mi][2], afr[mi][3], sAh + ro); \
            }                                                                   \
            _Pragma("unroll")                                                   \
            for (int mi = 0; mi < 4; mi++)                                      \
                _Pragma("unroll")                                               \
                for (int ni = 0; ni < 4; ni++)                                  \
                    MMA16816(acc[mi][ni], afr[mi][0], afr[mi][1], afr[mi][2],   \
                             afr[mi][3], bfr[ks][ni][0], bfr[ks][ni][1]);       \
        }                                                                       \
    } while (0)

// loader: per thread 2 rows x 16B for A and B each
#define GEMM_ISSUE_LOAD(st, kt, Aptr, Bptr)                                     \
    do {                                                                        \
        uint32_t s0 = sb + (st) * Q_STAGE_B;                                    \
        _Pragma("unroll")                                                       \
        for (int u = 0; u < 2; u++) {                                           \
            int row = u ? r1l : r0l;                                            \
            uint32_t so = row * G_RS + c16a * 2;                                \
            CP_ASYNC16(s0 + 0 * G_TILE_B + so,                                  \
                       (Aptr) + (size_t)(brow + row) * K + (kt) + c16a);        \
            CP_ASYNC16(s0 + 1 * G_TILE_B + so,                                  \
                       (Bptr) + (size_t)(bcol + row) * K + (kt) + c16a);        \
        }                                                                       \
    } while (0)

#define GEMM_MAINLOOP(Aptr, Bptr)                                               \
    do {                                                                        \
        const int nchunks = K / 32;                                             \
        GEMM_ISSUE_LOAD(0, 0,  (Aptr), (Bptr));  CP_COMMIT();                   \
        GEMM_ISSUE_LOAD(1, 32, (Aptr), (Bptr));  CP_COMMIT();                   \
        for (int ch = 0; ch < nchunks; ch++) {                                  \
            if (ch + 2 < nchunks) {                                             \
                GEMM_ISSUE_LOAD((ch + 2) & 3, (ch + 2) * 32, (Aptr), (Bptr));   \
                CP_COMMIT();                                                    \
                CP_WAIT(2);                                                     \
            } else if (ch + 1 < nchunks) {                                      \
                CP_WAIT(1);                                                     \
            } else {                                                            \
                CP_WAIT(0);                                                     \
            }                                                                   \
            __syncthreads();                                                    \
            GEMM_CHUNK(sb + (ch & 3) * Q_STAGE_B);                              \
        }                                                                       \
    } while (0)

// ---------------------------------------------------------------------------
// QKV GEMM: grid (N/128, M/128, 3); z selects W/bias/output; fp16 out.
// ---------------------------------------------------------------------------
__global__ __launch_bounds__(256, 2) void gemm_qkv(
    const __half* __restrict__ Ahi, const __half* __restrict__ Wt,
    const float* __restrict__ bq, const float* __restrict__ bk,
    const float* __restrict__ bv,
    __half* __restrict__ Qhi, __half* __restrict__ Khi, __half* __restrict__ Vhi,
    int M, int N, int K)
{
    extern __shared__ char smem[];
    const uint32_t sb = smem_u32(smem);
    const int z = blockIdx.z;
    const __half* Bh = Wt + (size_t)z * DD;
    const float* bias = (z == 0) ? bq : (z == 1) ? bk : bv;
    __half* Chi = (z == 0) ? Qhi : (z == 1) ? Khi : Vhi;

    const int tid = threadIdx.x, lane = tid & 31, wid = tid >> 5;
    const int brow = blockIdx.y * 128, bcol = blockIdx.x * 128;
    const int wm0 = (wid & 1) * 64;
    const int wn0 = (wid >> 1) * 32;

    float acc[4][4][4];
#pragma unroll
    for (int mi = 0; mi < 4; mi++)
#pragma unroll
        for (int ni = 0; ni < 4; ni++)
#pragma unroll
            for (int e = 0; e < 4; e++) acc[mi][ni][e] = 0.f;

    const int r0l = tid >> 2, c16a = (tid & 3) * 8;
    const int r1l = (tid + 256) >> 2;

    GEMM_MAINLOOP(Ahi, Bh);

    // epilogue: fp16 out
#pragma unroll
    for (int mi = 0; mi < 4; mi++) {
#pragma unroll
        for (int ni = 0; ni < 4; ni++) {
            int r = brow + wm0 + mi * 16 + (lane >> 2);
            int c = bcol + wn0 + ni * 8 + (lane & 3) * 2;
            float bx = bias[c], by = bias[c + 1];
            *(uint32_t*)&Chi[(size_t)r * N + c] =
                pack2h(acc[mi][ni][0] + bx, acc[mi][ni][1] + by);
            *(uint32_t*)&Chi[(size_t)(r + 8) * N + c] =
                pack2h(acc[mi][ni][2] + bx, acc[mi][ni][3] + by);
        }
    }
}

// ---------------------------------------------------------------------------
// O-projection GEMM: fp32 out; same mainloop.
// ---------------------------------------------------------------------------
__global__ __launch_bounds__(256, 2) void gemm_o(
    const __half* __restrict__ Ahi, const __half* __restrict__ Bhi,
    const float* __restrict__ bias, float* __restrict__ C,
    int M, int N, int K)
{
    extern __shared__ char smem[];
    const uint32_t sb = smem_u32(smem);
    const int tid = threadIdx.x, lane = tid & 31, wid = tid >> 5;
    const int brow = blockIdx.y * 128, bcol = blockIdx.x * 128;
    const int wm0 = (wid & 1) * 64;
    const int wn0 = (wid >> 1) * 32;

    float acc[4][4][4];
#pragma unroll
    for (int mi = 0; mi < 4; mi++)
#pragma unroll
        for (int ni = 0; ni < 4; ni++)
#pragma unroll
            for (int e = 0; e < 4; e++) acc[mi][ni][e] = 0.f;

    const int r0l = tid >> 2, c16a = (tid & 3) * 8;
    const int r1l = (tid + 256) >> 2;

    GEMM_MAINLOOP(Ahi, Bhi);

#pragma unroll
    for (int mi = 0; mi < 4; mi++) {
#pragma unroll
        for (int ni = 0; ni < 4; ni++) {
            int r = brow + wm0 + mi * 16 + (lane >> 2);
            int c = bcol + wn0 + ni * 8 + (lane & 3) * 2;
            float bx = bias[c], by = bias[c + 1];
            *(float2*)&C[(size_t)r * N + c] =
                make_float2(acc[mi][ni][0] + bx, acc[mi][ni][1] + by);
            *(float2*)&C[(size_t)(r + 8) * N + c] =
                make_float2(acc[mi][ni][2] + bx, acc[mi][ni][3] + by);
        }
    }
}

// ---------------------------------------------------------------------------
// Tensor-core banded attention (fp16, 1-pass QK and PV), base-2 softmax with
// packed ex2.approx.f16x2 (P fragments produced directly in fp16; l sums the
// exact fp16 p values, so normalization is common-mode exact).
// grid = (S/128, H, B), block = 256 (8 warps x 16 q-rows). fp16 output.
// ---------------------------------------------------------------------------
#define AT_RS    144                 // smem row stride bytes (72 fp16)
#define AT_QTILE (128 * AT_RS)       // 18432 B (Q: 128 rows)
#define AT_KTILE (64 * AT_RS)        // 9216 B  (K or V: 64 rows)
#define AT_SQH   0
#define AT_ST0   AT_QTILE
#define AT_STB   (2 * AT_KTILE)      // Kh, Vh per stage
#define AT_SMEM  (AT_QTILE + 2 * AT_STB)   // 55296 B

__global__ __launch_bounds__(256) void attn_tc(
    const __half* __restrict__ Qh, const __half* __restrict__ Kh,
    const __half* __restrict__ Vh, __half* __restrict__ Oh)
{
    extern __shared__ char smem[];
    const uint32_t sb = smem_u32(smem);
    const int qt = blockIdx.x, h = blockIdx.y, b = blockIdx.z;
    const int q0 = qt * 128;
    const int tid = threadIdx.x, lane = tid & 31, w = tid >> 5;
    const float scale_l2e = 0.125f * 1.4426950408889634f;  // scale * log2(e)

    const int qrow = tid >> 1;
    const int qhalf = (tid & 1) * 64;
    const int krow = tid >> 2;
    const int kquar = (tid & 3) * 32;

    const int kb_lo = max(0, q0 - (WINDOW - 1)) >> 6;
    const int kb_hi = (q0 + 127) >> 6;
    const int nch = kb_hi - kb_lo + 1;

    // prologue: Q + first K/V chunk
    {
        size_t g = ((size_t)(b * SEQ + q0 + qrow)) * DMODEL + h * DHEAD + (qhalf >> 1);
        uint32_t so = qrow * AT_RS + qhalf;
#pragma unroll
        for (int i = 0; i < 4; i++)
            CP_ASYNC16(sb + AT_SQH + so + i * 16, Qh + g + i * 8);
        size_t gk = ((size_t)(b * SEQ + kb_lo * 64 + krow)) * DMODEL + h * DHEAD + (kquar >> 1);
        uint32_t sko = krow * AT_RS + kquar;
        uint32_t s0 = sb + AT_ST0;
#pragma unroll
        for (int i = 0; i < 2; i++) {
            CP_ASYNC16(s0 + 0 * AT_KTILE + sko + i * 16, Kh + gk + i * 8);
            CP_ASYNC16(s0 + 1 * AT_KTILE + sko + i * 16, Vh + gk + i * 8);
        }
        CP_COMMIT();
    }

    float m0 = -1e30f, m1 = -1e30f, l0 = 0.f, l1 = 0.f;   // m in log2 domain
    float oacc[8][4];
#pragma unroll
    for (int t = 0; t < 8; t++)
#pragma unroll
        for (int e = 0; e < 4; e++) oacc[t][e] = 0.f;

    const int r0g = q0 + w * 16 + (lane >> 2);
    const int r1g = r0g + 8;
    const int wlo = q0 + w * 16;
    const int whi = wlo + 15;

    for (int i = 0; i < nch; i++) {
        const int kb = kb_lo + i;
        if (i + 1 < nch) {
            size_t gk = ((size_t)(b * SEQ + (kb + 1) * 64 + krow)) * DMODEL + h * DHEAD + (kquar >> 1);
            uint32_t sko = krow * AT_RS + kquar;
            uint32_t s0 = sb + AT_ST0 + ((i + 1) & 1) * AT_STB;
#pragma unroll
            for (int u = 0; u < 2; u++) {
                CP_ASYNC16(s0 + 0 * AT_KTILE + sko + u * 16, Kh + gk + u * 8);
                CP_ASYNC16(s0 + 1 * AT_KTILE + sko + u * 16, Vh + gk + u * 8);
            }
            CP_COMMIT();
            CP_WAIT(1);
        } else {
            CP_WAIT(0);
        }
        __syncthreads();

        const int kbase = kb * 64;
        if (kbase <= whi && kbase + 63 >= wlo - (WINDOW - 1)) {
            const uint32_t s0  = sb + AT_ST0 + (i & 1) * AT_STB;
            const uint32_t sKh = s0;
            const uint32_t sVh = s0 + AT_KTILE;

            // ---- S = Q K^T (1-pass) ----
            float sacc[8][4];
#pragma unroll
            for (int t = 0; t < 8; t++)
#pragma unroll
                for (int e = 0; e < 4; e++) sacc[t][e] = 0.f;

#pragma unroll
            for (int ks = 0; ks < 4; ks++) {
                const uint32_t kbb = ks * 32;
                uint32_t aro = (w * 16 + (lane & 15)) * AT_RS + kbb + (lane >> 4) * 16;
                uint32_t ah[4];
                LDSM_X4(ah[0], ah[1], ah[2], ah[3], sb + AT_SQH + aro);
#pragma unroll
                for (int np = 0; np < 4; np++) {
                    uint32_t ro = (np * 16 + (lane & 7) + ((lane >> 4) & 1) * 8) * AT_RS
                                  + kbb + ((lane >> 3) & 1) * 16;
                    uint32_t bh[4];
                    LDSM_X4(bh[0], bh[1], bh[2], bh[3], sKh + ro);
                    MMA16816(sacc[2*np],   ah[0], ah[1], ah[2], ah[3], bh[0], bh[1]);
                    MMA16816(sacc[2*np+1], ah[0], ah[1], ah[2], ah[3], bh[2], bh[3]);
                }
            }

            // ---- mask (base-2 domain) + row max ----
            float cmax0 = -1e30f, cmax1 = -1e30f;
#pragma unroll
            for (int t = 0; t < 8; t++) {
                const int c0 = kbase + t * 8 + 2 * (lane & 3);
                int d00 = r0g - c0, d01 = r0g - (c0 + 1);
                int d10 = r1g - c0, d11 = r1g - (c0 + 1);
                sacc[t][0] = (d00 >= 0 && d00 < WINDOW) ? sacc[t][0] * scale_l2e : -1e30f;
                sacc[t][1] = (d01 >= 0 && d01 < WINDOW) ? sacc[t][1] * scale_l2e : -1e30f;
                sacc[t][2] = (d10 >= 0 && d10 < WINDOW) ? sacc[t][2] * scale_l2e : -1e30f;
                sacc[t][3] = (d11 >= 0 && d11 < WINDOW) ? sacc[t][3] * scale_l2e : -1e30f;
                cmax0 = fmaxf(cmax0, fmaxf(sacc[t][0], sacc[t][1]));
                cmax1 = fmaxf(cmax1, fmaxf(sacc[t][2], sacc[t][3]));
            }
            cmax0 = fmaxf(cmax0, __shfl_xor_sync(0xffffffffu, cmax0, 1));
            cmax0 = fmaxf(cmax0, __shfl_xor_sync(0xffffffffu, cmax0, 2));
            cmax1 = fmaxf(cmax1, __shfl_xor_sync(0xffffffffu, cmax1, 1));
            cmax1 = fmaxf(cmax1, __shfl_xor_sync(0xffffffffu, cmax1, 2));

            float mn0 = fmaxf(m0, cmax0), mn1 = fmaxf(m1, cmax1);
            float a0 = ex2f(m0 - mn0), a1 = ex2f(m1 - mn1);

            // ---- packed 2^x -> fp16 P fragments; fp32 row-sums of the same p ----
            uint32_t ph[8][2];
            float rs0 = 0.f, rs1 = 0.f;
#pragma unroll
            for (int t = 0; t < 8; t++) {
                ph[t][0] = ex2_f16x2(sacc[t][0] - mn0, sacc[t][1] - mn0);
                ph[t][1] = ex2_f16x2(sacc[t][2] - mn1, sacc[t][3] - mn1);
                float2 f0 = __half22float2(*(__half2*)&ph[t][0]);
                float2 f1 = __half22float2(*(__half2*)&ph[t][1]);
                rs0 += f0.x + f0.y;
                rs1 += f1.x + f1.y;
            }
            rs0 += __shfl_xor_sync(0xffffffffu, rs0, 1);
            rs0 += __shfl_xor_sync(0xffffffffu, rs0, 2);
            rs1 += __shfl_xor_sync(0xffffffffu, rs1, 1);
            rs1 += __shfl_xor_sync(0xffffffffu, rs1, 2);
            l0 = l0 * a0 + rs0;  m0 = mn0;
            l1 = l1 * a1 + rs1;  m1 = mn1;
#pragma unroll
            for (int t = 0; t < 8; t++) {
                oacc[t][0] *= a0; oacc[t][1] *= a0;
                oacc[t][2] *= a1; oacc[t][3] *= a1;
            }

            // ---- PV (P fragments already fp16; V via ldmatrix.trans) ----
#pragma unroll
            for (int ks = 0; ks < 4; ks++) {
                uint32_t aph[4];
                aph[0] = ph[2*ks][0];
                aph[1] = ph[2*ks][1];
                aph[2] = ph[2*ks+1][0];
                aph[3] = ph[2*ks+1][1];
#pragma unroll
                for (int np = 0; np < 4; np++) {
                    uint32_t vro = (ks * 16 + (lane & 7) + ((lane >> 3) & 1) * 8) * AT_RS
                                   + np * 32 + (lane >> 4) * 16;
                    uint32_t vh[4];
                    LDSM_X4_T(vh[0], vh[1], vh[2], vh[3], sVh + vro);
                    MMA16816(oacc[2*np],   aph[0], aph[1], aph[2], aph[3], vh[0], vh[1]);
                    MMA16816(oacc[2*np+1], aph[0], aph[1], aph[2], aph[3], vh[2], vh[3]);
                }
            }
        }
        __syncthreads();
    }

    // ---- epilogue: divide by l, plain fp16 store ----
    const float inv0 = 1.f / l0, inv1 = 1.f / l1;
    const size_t row0 = (size_t)(b * SEQ + r0g) * DMODEL;
    const size_t row1 = (size_t)(b * SEQ + r1g) * DMODEL;
#pragma unroll
    for (int t = 0; t < 8; t++) {
        const int c = h * DHEAD + t * 8 + 2 * (lane & 3);
        *(uint32_t*)&Oh[row0 + c] = pack2h(oacc[t][0] * inv0, oacc[t][1] * inv0);
        *(uint32_t*)&Oh[row1 + c] = pack2h(oacc[t][2] * inv1, oacc[t][3] * inv1);
    }
}

// ---------------------------------------------------------------------------
// Launch
// ---------------------------------------------------------------------------
extern "C" void kernel_launch(void* const* d_in, const int* in_sizes, int n_in,
                              void* d_out, int out_size)
{
    const float* X  = (const float*)d_in[0];
    const float* Wq = (const float*)d_in[1];
    const float* bq = (const float*)d_in[2];
    const float* Wk = (const float*)d_in[3];
    const float* bk = (const float*)d_in[4];
    const float* Wv = (const float*)d_in[5];
    const float* bv = (const float*)d_in[6];
    const float* Wo = (const float*)d_in[7];
    const float* bo = (const float*)d_in[8];
    float* out = (float*)d_out;

    __half *xhi, *qhi, *khi, *vhi, *aohi, *wthi;
    cudaGetSymbolAddress((void**)&xhi,  g_xhi);
    cudaGetSymbolAddress((void**)&qhi,  g_qhi);
    cudaGetSymbolAddress((void**)&khi,  g_khi);
    cudaGetSymbolAddress((void**)&vhi,  g_vhi);
    cudaGetSymbolAddress((void**)&aohi, g_aohi);
    cudaGetSymbolAddress((void**)&wthi, g_wthi);

    cudaFuncSetAttribute(attn_tc,  cudaFuncAttributeMaxDynamicSharedMemorySize, AT_SMEM);
    cudaFuncSetAttribute(gemm_qkv, cudaFuncAttributeMaxDynamicSharedMemorySize, Q_SMEM_B);
    cudaFuncSetAttribute(gemm_o,   cudaFuncAttributeMaxDynamicSharedMemorySize, Q_SMEM_B);

    // 1. prep: X convert + all 4 weight transposes in one launch
    prep_kernel<<<dim3(32, 32, 5), dim3(32, 8)>>>(X, Wq, Wk, Wv, Wo, xhi, wthi);

    // 2. fused Q/K/V projections (1-pass fp16, 128x128 tiles, BK=32, 4-stage)
    gemm_qkv<<<dim3(DMODEL / 128, MROWS / 128, 3), 256, Q_SMEM_B>>>(
        xhi, wthi, bq, bk, bv, qhi, khi, vhi, MROWS, DMODEL, DMODEL);

    // 3. tensor-core banded attention (128-query tiles, f16x2 ex2 softmax)
    attn_tc<<<dim3(SEQ / 128, NHEADS, BATCH), 256, AT_SMEM>>>(qhi, khi, vhi, aohi);

    // 4. O projection (1-pass, 128x128 tiles, BK=32, 4-stage) -> fp32 output
    gemm_o<<<dim3(DMODEL / 128, MROWS / 128), 256, Q_SMEM_B>>>(
        aohi, wthi + 3 * DD, bo, out, MROWS, DMODEL, DMODEL);
}